// round 1
// baseline (speedup 1.0000x reference)
#include <cuda_runtime.h>
#include <cuda_bf16.h>

#define NS 2000
#define NH 64
#define NB 1024

// Scratch for rel_encoded [S, H] (no cudaMalloc allowed)
__device__ float g_rel_enc[NS * NH];

// ---------------------------------------------------------------------------
// Kernel 1: rel_enc[s,:] = mask(s) * ( relu(rel[idx,s,:] @ W1^T + b1) @ W2^T + b2 )
// 256 threads = 4 rows per block; W1/W2 staged in padded shared memory.
// ---------------------------------------------------------------------------
__global__ __launch_bounds__(256)
void mlp_kernel(const int* __restrict__ stock_idx,
                const float* __restrict__ rel,
                const float* __restrict__ W1,
                const float* __restrict__ b1,
                const float* __restrict__ W2,
                const float* __restrict__ b2)
{
    __shared__ float W1s[NH * 65];   // padded: row j at j*65, bank-conflict free
    __shared__ float W2s[NH * 65];
    __shared__ float rowbuf[4 * NH];
    __shared__ float hbuf[4 * NH];

    const int t = threadIdx.x;
    const int r = t >> 6;      // row-within-block 0..3
    const int j = t & 63;      // hidden index 0..63
    const int idx = *stock_idx;
    const int s = blockIdx.x * 4 + r;

    // Stage W1, W2 into shared (coalesced gmem reads)
    for (int i = t; i < NH * NH; i += 256) {
        W1s[(i >> 6) * 65 + (i & 63)] = W1[i];
        W2s[(i >> 6) * 65 + (i & 63)] = W2[i];
    }

    // Load this block's 4 relationship rows
    rowbuf[r * NH + j] = rel[(size_t)idx * NS * NH + (size_t)s * NH + j];
    __syncthreads();

    // layer 1: h[j] = relu(b1[j] + sum_k row[k] * W1[j,k])
    float acc = b1[j];
    #pragma unroll 16
    for (int k = 0; k < NH; k++)
        acc = fmaf(rowbuf[r * NH + k], W1s[j * 65 + k], acc);
    hbuf[r * NH + j] = fmaxf(acc, 0.0f);
    __syncthreads();

    // layer 2: o[j] = b2[j] + sum_k h[k] * W2[j,k]
    float acc2 = b2[j];
    #pragma unroll 16
    for (int k = 0; k < NH; k++)
        acc2 = fmaf(hbuf[r * NH + k], W2s[j * 65 + k], acc2);

    if (s == idx) acc2 = 0.0f;   // exclude i == stock_idx
    g_rel_enc[s * NH + j] = acc2;
}

// ---------------------------------------------------------------------------
// Kernel 2: out[b,h] = sum_s enc[b,s,h] * rel_enc[s,h]
// One block per batch row. Thread (srow = t>>4, h16 = t&15) accumulates a
// float4; fully coalesced 128-bit streaming loads; shared tree-reduction.
// ---------------------------------------------------------------------------
__global__ __launch_bounds__(256)
void reduce_kernel(const float4* __restrict__ enc,  // [B, S, 16] float4
                   float4* __restrict__ out)        // [B, 16]    float4
{
    const int b = blockIdx.x;
    const int t = threadIdx.x;
    const int h16  = t & 15;   // float4 index within hidden dim
    const int srow = t >> 4;   // 0..15

    const float4* __restrict__ encB = enc + (size_t)b * NS * (NH / 4);
    const float4* __restrict__ rel4 = (const float4*)g_rel_enc;

    float4 acc = make_float4(0.f, 0.f, 0.f, 0.f);

    #pragma unroll 5
    for (int s = srow; s < NS; s += 16) {
        const float4 e = encB[s * 16 + h16];
        const float4 rv = rel4[s * 16 + h16];
        acc.x = fmaf(e.x, rv.x, acc.x);
        acc.y = fmaf(e.y, rv.y, acc.y);
        acc.z = fmaf(e.z, rv.z, acc.z);
        acc.w = fmaf(e.w, rv.w, acc.w);
    }

    __shared__ float4 red[256];
    red[t] = acc;
    __syncthreads();

    #pragma unroll
    for (int off = 128; off >= 16; off >>= 1) {
        if (t < off) {
            float4 a = red[t], bb = red[t + off];
            a.x += bb.x; a.y += bb.y; a.z += bb.z; a.w += bb.w;
            red[t] = a;
        }
        __syncthreads();
    }

    if (t < 16)
        out[b * 16 + t] = red[t];
}

// ---------------------------------------------------------------------------
// Inputs (metadata order):
//   d_in[0] stock_idx            int32   [1]
//   d_in[1] encoded_states       f32     [1024, 2000, 64]
//   d_in[2] relationship_matrix  f32     [2000, 2000, 64]
//   d_in[3] W1                   f32     [64, 64]
//   d_in[4] b1                   f32     [64]
//   d_in[5] W2                   f32     [64, 64]
//   d_in[6] b2                   f32     [64]
// Output: f32 [1024, 64]
// ---------------------------------------------------------------------------
extern "C" void kernel_launch(void* const* d_in, const int* in_sizes, int n_in,
                              void* d_out, int out_size)
{
    const int*   stock_idx = (const int*)  d_in[0];
    const float* enc       = (const float*)d_in[1];
    const float* rel       = (const float*)d_in[2];
    const float* W1        = (const float*)d_in[3];
    const float* b1        = (const float*)d_in[4];
    const float* W2        = (const float*)d_in[5];
    const float* b2        = (const float*)d_in[6];
    float* out = (float*)d_out;

    mlp_kernel<<<NS / 4, 256>>>(stock_idx, rel, W1, b1, W2, b2);
    reduce_kernel<<<NB, 256>>>((const float4*)enc, (float4*)out);
}

// round 2
// speedup vs baseline: 1.0701x; 1.0701x over previous
#include <cuda_runtime.h>
#include <cuda_bf16.h>

#define NS 2000
#define NH 64
#define NB 1024
#define NQ 4              // s-dimension split per batch row
#define SQ (NS / NQ)      // 500 s-rows per tile

// Scratch for rel_encoded [S, H] (no cudaMalloc allowed)
__device__ float g_rel_enc[NS * NH];

// ---------------------------------------------------------------------------
// Kernel 1: rel_enc[s,:] = mask(s) * ( relu(rel[idx,s,:] @ W1^T + b1) @ W2^T + b2 )
// Also zero-initializes the output buffer (poisoned by harness), so the
// reduce kernel can accumulate with atomics.
// ---------------------------------------------------------------------------
__global__ __launch_bounds__(256)
void mlp_kernel(const int* __restrict__ stock_idx,
                const float* __restrict__ rel,
                const float* __restrict__ W1,
                const float* __restrict__ b1,
                const float* __restrict__ W2,
                const float* __restrict__ b2,
                float* __restrict__ out)
{
    __shared__ float W1s[NH * 65];   // padded rows -> bank-conflict free
    __shared__ float W2s[NH * 65];
    __shared__ float rowbuf[4 * NH];
    __shared__ float hbuf[4 * NH];

    const int t = threadIdx.x;
    const int r = t >> 6;      // row-within-block 0..3
    const int j = t & 63;      // hidden index 0..63
    const int idx = *stock_idx;
    const int s = blockIdx.x * 4 + r;

    // Zero the output (grid-stride over 1024*64 = 65536 elements)
    for (int i = blockIdx.x * 256 + t; i < NB * NH; i += gridDim.x * 256)
        out[i] = 0.0f;

    // Stage W1, W2 into shared (coalesced)
    for (int i = t; i < NH * NH; i += 256) {
        W1s[(i >> 6) * 65 + (i & 63)] = W1[i];
        W2s[(i >> 6) * 65 + (i & 63)] = W2[i];
    }

    // Load this block's 4 relationship rows
    rowbuf[r * NH + j] = rel[(size_t)idx * NS * NH + (size_t)s * NH + j];
    __syncthreads();

    // layer 1
    float acc = b1[j];
    #pragma unroll 16
    for (int k = 0; k < NH; k++)
        acc = fmaf(rowbuf[r * NH + k], W1s[j * 65 + k], acc);
    hbuf[r * NH + j] = fmaxf(acc, 0.0f);
    __syncthreads();

    // layer 2
    float acc2 = b2[j];
    #pragma unroll 16
    for (int k = 0; k < NH; k++)
        acc2 = fmaf(hbuf[r * NH + k], W2s[j * 65 + k], acc2);

    if (s == idx) acc2 = 0.0f;   // exclude i == stock_idx
    g_rel_enc[s * NH + j] = acc2;
}

// ---------------------------------------------------------------------------
// Kernel 2: out[b,h] += sum_{s in quarter} enc[b,s,h] * rel_enc[s,h]
// grid = NB*NQ tiles (4096) for fine-grained load balance across 148 SMs.
// enc read with __ldcs (streaming, evict-first); rel_enc stays L2/L1 hot.
// ---------------------------------------------------------------------------
__global__ __launch_bounds__(256)
void reduce_kernel(const float4* __restrict__ enc,  // [B, S, 16] float4
                   float* __restrict__ out)         // [B, 64]
{
    const int tile = blockIdx.x;
    const int b = tile >> 2;           // batch row
    const int q = tile & 3;            // s-quarter
    const int t = threadIdx.x;
    const int h16  = t & 15;           // float4 lane within hidden dim
    const int srow = t >> 4;           // 0..15

    const float4* __restrict__ encB = enc + (size_t)b * NS * (NH / 4);
    const float4* __restrict__ rel4 = (const float4*)g_rel_enc;

    const int s_base = q * SQ;
    const int s_end  = s_base + SQ;

    float4 acc = make_float4(0.f, 0.f, 0.f, 0.f);

    #pragma unroll 4
    for (int s = s_base + srow; s < s_end; s += 16) {
        const float4 e  = __ldcs(&encB[s * 16 + h16]);   // stream, don't cache
        const float4 rv = rel4[s * 16 + h16];            // L2/L1 resident
        acc.x = fmaf(e.x, rv.x, acc.x);
        acc.y = fmaf(e.y, rv.y, acc.y);
        acc.z = fmaf(e.z, rv.z, acc.z);
        acc.w = fmaf(e.w, rv.w, acc.w);
    }

    __shared__ float4 red[256];
    red[t] = acc;
    __syncthreads();

    #pragma unroll
    for (int off = 128; off >= 16; off >>= 1) {
        if (t < off) {
            float4 a = red[t], bb = red[t + off];
            a.x += bb.x; a.y += bb.y; a.z += bb.z; a.w += bb.w;
            red[t] = a;
        }
        __syncthreads();
    }

    // 64 scalar partials -> global accumulate (4 tiles hit each address)
    if (t < 64) {
        const float v = ((const float*)red)[t];
        atomicAdd(&out[b * NH + t], v);
    }
}

// ---------------------------------------------------------------------------
// Inputs (metadata order):
//   d_in[0] stock_idx            int32   [1]
//   d_in[1] encoded_states       f32     [1024, 2000, 64]
//   d_in[2] relationship_matrix  f32     [2000, 2000, 64]
//   d_in[3] W1  f32 [64,64]   d_in[4] b1 f32 [64]
//   d_in[5] W2  f32 [64,64]   d_in[6] b2 f32 [64]
// Output: f32 [1024, 64]
// ---------------------------------------------------------------------------
extern "C" void kernel_launch(void* const* d_in, const int* in_sizes, int n_in,
                              void* d_out, int out_size)
{
    const int*   stock_idx = (const int*)  d_in[0];
    const float* enc       = (const float*)d_in[1];
    const float* rel       = (const float*)d_in[2];
    const float* W1        = (const float*)d_in[3];
    const float* b1        = (const float*)d_in[4];
    const float* W2        = (const float*)d_in[5];
    const float* b2        = (const float*)d_in[6];
    float* out = (float*)d_out;

    mlp_kernel<<<NS / 4, 256>>>(stock_idx, rel, W1, b1, W2, b2, out);
    reduce_kernel<<<NB * NQ, 256>>>((const float4*)enc, out);
}